// round 1
// baseline (speedup 1.0000x reference)
#include <cuda_runtime.h>
#include <cstdint>

// Forward 5/3 lifting wavelet transform, 2D separable, fused.
// x: (8, 32, 512, 512) f32  ->  out: (8, 128, 256, 256) f32
// out channels: [LL(0:32) | LH(32:64) | HL(64:96) | HH(96:128)]
//
// Lifting (derived exactly from the JAX reference, incl. its reflect):
//   d[i] = x[2i+1] - 0.5*(even[refl(i-1)] + even[refl(i+1)])
//   s[i] = x[2i]   + 0.25*(d[refl(i-1)] + d[refl(i+1)])
// refl: -1 -> 1, 256 -> 254  (N=256 coefficients per 512-length axis)

static constexpr int H = 512;
static constexpr int Wd = 512;
static constexpr int R = 16;        // output rows per strip
static constexpr int NSTRIP = 256 / R;   // 16
static constexpr int NBC = 8 * 32;       // 256 images
static constexpr int MAXROWS = 2 * R + 7; // 39
static constexpr int SMEM_BYTES = MAXROWS * Wd * 4; // 79872

__global__ __launch_bounds__(512, 2)
void lwt53_fused_kernel(const float* __restrict__ x, float* __restrict__ out) {
    extern __shared__ float A[];   // [nrows][512]

    const int blk   = blockIdx.x;
    const int strip = blk & (NSTRIP - 1);
    const int bc    = blk >> 4;          // log2(NSTRIP)=4
    const int r0    = strip * R;

    const int mlo   = max(0, 2 * r0 - 4);
    const int mhi   = min(H - 1, 2 * r0 + 2 * R + 2);
    const int nrows = mhi - mlo + 1;

    const float* __restrict__ xim = x + (size_t)bc * (H * Wd) + (size_t)mlo * Wd;

    const int tid = threadIdx.x;
    const int NT  = blockDim.x;

    // ---- Phase 1: load tile (float4, coalesced) ----
    {
        const float4* __restrict__ x4 = reinterpret_cast<const float4*>(xim);
        float4* A4 = reinterpret_cast<float4*>(A);
        const int n4 = nrows * (Wd / 4);
        for (int idx = tid; idx < n4; idx += NT)
            A4[idx] = x4[idx];
    }
    __syncthreads();

    // ---- Phase 2: row predict (d into odd slots, in place) ----
    {
        const int nd = nrows * 256;
        for (int idx = tid; idx < nd; idx += NT) {
            const int r = idx >> 8;
            const int i = idx & 255;
            const int il = (i == 0)   ? 1   : i - 1;
            const int ir = (i == 255) ? 254 : i + 1;
            float* row = A + r * Wd;
            const float d = row[2 * i + 1] - 0.5f * (row[2 * il] + row[2 * ir]);
            row[2 * i + 1] = d;
        }
    }
    __syncthreads();

    // ---- Phase 3: row update (s into even slots, in place) ----
    {
        const int nd = nrows * 256;
        for (int idx = tid; idx < nd; idx += NT) {
            const int r = idx >> 8;
            const int i = idx & 255;
            const int il = (i == 0)   ? 1   : i - 1;
            const int ir = (i == 255) ? 254 : i + 1;
            float* row = A + r * Wd;
            row[2 * i] += 0.25f * (row[2 * il + 1] + row[2 * ir + 1]);
        }
    }
    __syncthreads();

    // ---- Phase 4: column predict (dc into odd rows, float4 across cols) ----
    {
        const int jlo = max(0, r0 - 1);
        const int jhi = min(255, r0 + R);
        const int nit = (jhi - jlo + 1) * (Wd / 4);
        for (int idx = tid; idx < nit; idx += NT) {
            const int j  = jlo + (idx >> 7);
            const int c4 = idx & 127;
            const int jm = (j == 0)   ? 1   : j - 1;
            const int jp = (j == 255) ? 254 : j + 1;
            float4* rowO = reinterpret_cast<float4*>(A + (2 * j + 1 - mlo) * Wd);
            const float4 va = reinterpret_cast<const float4*>(A + (2 * jm - mlo) * Wd)[c4];
            const float4 vb = reinterpret_cast<const float4*>(A + (2 * jp - mlo) * Wd)[c4];
            float4 vo = rowO[c4];
            vo.x -= 0.5f * (va.x + vb.x);
            vo.y -= 0.5f * (va.y + vb.y);
            vo.z -= 0.5f * (va.z + vb.z);
            vo.w -= 0.5f * (va.w + vb.w);
            rowO[c4] = vo;
        }
    }
    __syncthreads();

    // ---- Phase 5: column update (sc into even rows, float4 across cols) ----
    {
        const int nit = R * (Wd / 4);
        for (int idx = tid; idx < nit; idx += NT) {
            const int k  = r0 + (idx >> 7);
            const int c4 = idx & 127;
            const int km = (k == 0)   ? 1   : k - 1;
            const int kp = (k == 255) ? 254 : k + 1;
            float4* rowE = reinterpret_cast<float4*>(A + (2 * k - mlo) * Wd);
            const float4 va = reinterpret_cast<const float4*>(A + (2 * km + 1 - mlo) * Wd)[c4];
            const float4 vb = reinterpret_cast<const float4*>(A + (2 * kp + 1 - mlo) * Wd)[c4];
            float4 ve = rowE[c4];
            ve.x += 0.25f * (va.x + vb.x);
            ve.y += 0.25f * (va.y + vb.y);
            ve.z += 0.25f * (va.z + vb.z);
            ve.w += 0.25f * (va.w + vb.w);
            rowE[c4] = ve;
        }
    }
    __syncthreads();

    // ---- Phase 6: write 4 subbands (float2 smem reads, coalesced STG) ----
    {
        const int b = bc >> 5;
        const int c = bc & 31;
        const size_t band = (size_t)256 * 256;
        float* __restrict__ LL = out + ((size_t)b * 128 + c) * band;
        float* __restrict__ LH = LL + 32 * band;
        float* __restrict__ HL = LL + 64 * band;
        float* __restrict__ HH = LL + 96 * band;

        const int nit = R * 256;
        for (int idx = tid; idx < nit; idx += NT) {
            const int k = r0 + (idx >> 8);
            const int i = idx & 255;
            const float2 sv = reinterpret_cast<const float2*>(A + (2 * k     - mlo) * Wd)[i];
            const float2 dv = reinterpret_cast<const float2*>(A + (2 * k + 1 - mlo) * Wd)[i];
            const size_t o = (size_t)k * 256 + i;
            LL[o] = sv.x;
            HL[o] = sv.y;
            LH[o] = dv.x;
            HH[o] = dv.y;
        }
    }
}

extern "C" void kernel_launch(void* const* d_in, const int* in_sizes, int n_in,
                              void* d_out, int out_size) {
    const float* x = (const float*)d_in[0];
    float* out = (float*)d_out;
    (void)in_sizes; (void)n_in; (void)out_size;

    static bool attr_set = false;
    if (!attr_set) {
        cudaFuncSetAttribute(lwt53_fused_kernel,
                             cudaFuncAttributeMaxDynamicSharedMemorySize, SMEM_BYTES);
        attr_set = true;
    }

    dim3 grid(NBC * NSTRIP);   // 4096
    dim3 block(512);
    lwt53_fused_kernel<<<grid, block, SMEM_BYTES>>>(x, out);
}

// round 2
// speedup vs baseline: 1.7941x; 1.7941x over previous
#include <cuda_runtime.h>
#include <cstdint>

// Forward 5/3 lifting wavelet, 2D separable, fused, register-heavy.
// x: (8, 32, 512, 512) f32 -> out: (8, 128, 256, 256) f32
// out channels: [LL(0:32) | LH(32:64) | HL(64:96) | HH(96:128)]
//
//   d[i] = x[2i+1] - 0.5*(even[refl(i-1)] + even[refl(i+1)])
//   s[i] = x[2i]   + 0.25*(d[refl(i-1)] + d[refl(i+1)])
// refl: -1 -> 1, 256 -> 254

static constexpr int H = 512;
static constexpr int Wd = 512;
static constexpr int R = 16;              // output rows per strip
static constexpr int NSTRIP = 256 / R;    // 16
static constexpr int NBC = 8 * 32;        // 256 images
static constexpr int MAXROWS = 2 * R + 7; // 39
static constexpr int SMEM_BYTES = MAXROWS * Wd * 4; // 79872

__global__ __launch_bounds__(512, 2)
void lwt53_fused_kernel(const float* __restrict__ x, float* __restrict__ out) {
    extern __shared__ float A[];   // [nrows][512]; per row: s in [0,256), d in [256,512)

    const unsigned FULL = 0xffffffffu;
    const int blk   = blockIdx.x;
    const int strip = blk & (NSTRIP - 1);
    const int bc    = blk >> 4;
    const int r0    = strip * R;

    const int mlo   = max(0, 2 * r0 - 4);
    const int mhi   = min(H - 1, 2 * r0 + 2 * R + 2);
    const int nrows = mhi - mlo + 1;

    const float* __restrict__ xim = x + (size_t)bc * (H * Wd) + (size_t)mlo * Wd;

    const int tid  = threadIdx.x;
    const int warp = tid >> 5;
    const int lane = tid & 31;

    // ================= Phase A: row lifting in registers =================
    // Warp handles whole rows. Lane l owns coefficient pairs (64j+2l, 64j+2l+1)
    // for j=0..3 — exactly what one coalesced float4 load delivers.
    for (int r = warp; r < nrows; r += 16) {
        const float4* __restrict__ xr =
            reinterpret_cast<const float4*>(xim + (size_t)r * Wd);
        float eA[4], oA[4], eB[4], oB[4];
        #pragma unroll
        for (int j = 0; j < 4; j++) {
            const float4 v = xr[32 * j + lane];
            eA[j] = v.x; oA[j] = v.y; eB[j] = v.z; oB[j] = v.w;
        }

        // predict: d
        float dA[4], dB[4];
        #pragma unroll
        for (int j = 0; j < 4; j++) {
            float up = __shfl_up_sync(FULL, eB[j], 1);                 // lane-1 eB
            float cp = __shfl_sync(FULL, (j > 0) ? eB[j - 1] : eB[j], 31);
            float Eprev = (lane == 0) ? ((j == 0) ? eB[0] : cp) : up;  // refl at i=0
            float dn = __shfl_down_sync(FULL, eA[j], 1);               // lane+1 eA
            float cn = __shfl_sync(FULL, (j < 3) ? eA[j + 1] : eA[j], 0);
            float Enext = (lane == 31) ? ((j == 3) ? eA[3] : cn) : dn; // refl at i=255
            dA[j] = oA[j] - 0.5f * (Eprev + eB[j]);
            dB[j] = oB[j] - 0.5f * (eA[j] + Enext);
        }

        // update: s, then store de-interleaved (s | d) as float2 (conflict-free)
        float* Arow = A + r * Wd;
        float2* __restrict__ srow = reinterpret_cast<float2*>(Arow);
        float2* __restrict__ drow = reinterpret_cast<float2*>(Arow + 256);
        #pragma unroll
        for (int j = 0; j < 4; j++) {
            float up = __shfl_up_sync(FULL, dB[j], 1);
            float cp = __shfl_sync(FULL, (j > 0) ? dB[j - 1] : dB[j], 31);
            float Dprev = (lane == 0) ? ((j == 0) ? dB[0] : cp) : up;
            float dn = __shfl_down_sync(FULL, dA[j], 1);
            float cn = __shfl_sync(FULL, (j < 3) ? dA[j + 1] : dA[j], 0);
            float Dnext = (lane == 31) ? ((j == 3) ? dA[3] : cn) : dn;
            float sA = eA[j] + 0.25f * (Dprev + dB[j]);
            float sB = eB[j] + 0.25f * (dA[j] + Dnext);
            srow[32 * j + lane] = make_float2(sA, sB);
            drow[32 * j + lane] = make_float2(dA[j], dB[j]);
        }
    }
    __syncthreads();

    // ================= Phase B: column lifting in registers =================
    // Thread t owns smem column t (t<256: s-rows -> LL/LH; t>=256: d-rows -> HL/HH).
    // Scalar LDS across consecutive threads = coalesced, conflict-free.
    {
        const int t = tid;
        float d[18];
        #pragma unroll
        for (int q = 0; q < 18; q++) {
            int j = r0 - 1 + q;
            j = (j < 0) ? 1 : ((j > 255) ? 254 : j);               // refl
            const int ro = (2 * j + 1) - mlo;
            const int rp = 2 * ((j == 0)   ? 1   : j - 1) - mlo;   // refl even prev
            const int rn = 2 * ((j == 255) ? 254 : j + 1) - mlo;   // refl even next
            d[q] = A[ro * Wd + t] - 0.5f * (A[rp * Wd + t] + A[rn * Wd + t]);
        }

        const int b = bc >> 5;
        const int c = bc & 31;
        const size_t band = (size_t)256 * 256;
        float* __restrict__ base = out + ((size_t)b * 128 + c) * band;
        // t<256: sOut=LL, dOut=LH ; t>=256: sOut=HL, dOut=HH
        float* __restrict__ sOut = base + ((t < 256) ? (size_t)0 : 64 * band);
        float* __restrict__ dOut = base + ((t < 256) ? 32 * band : 96 * band);
        const int col = t & 255;

        #pragma unroll
        for (int q = 0; q < 16; q++) {
            const int k = r0 + q;
            const float s = A[(2 * k - mlo) * Wd + t] + 0.25f * (d[q] + d[q + 2]);
            const size_t o = (size_t)k * 256 + col;
            sOut[o] = s;
            dOut[o] = d[q + 1];
        }
    }
}

extern "C" void kernel_launch(void* const* d_in, const int* in_sizes, int n_in,
                              void* d_out, int out_size) {
    const float* x = (const float*)d_in[0];
    float* out = (float*)d_out;
    (void)in_sizes; (void)n_in; (void)out_size;

    static bool attr_set = false;
    if (!attr_set) {
        cudaFuncSetAttribute(lwt53_fused_kernel,
                             cudaFuncAttributeMaxDynamicSharedMemorySize, SMEM_BYTES);
        attr_set = true;
    }

    dim3 grid(NBC * NSTRIP);   // 4096
    dim3 block(512);
    lwt53_fused_kernel<<<grid, block, SMEM_BYTES>>>(x, out);
}